// round 1
// baseline (speedup 1.0000x reference)
#include <cuda_runtime.h>

// -------------------------------------------------------------------------
// CustomGraphConv: per-edge MLP + scatter-sum + residual + node MLP, fp32.
// Round 1: SIMT fp32 with packed fma.rn.f32x2 (FFMA2) register-blocked GEMMs.
// -------------------------------------------------------------------------

#define FEAT 128
#define MAX_NODES 50000

// scratch: aggregated node features (residual pre-loaded)
static __device__ float g_agg[(size_t)MAX_NODES * FEAT];

// ---- packed f32x2 helpers ----
__device__ __forceinline__ unsigned long long pk2(float lo, float hi) {
    unsigned long long r;
    asm("mov.b64 %0, {%1, %2};" : "=l"(r) : "f"(lo), "f"(hi));
    return r;
}
__device__ __forceinline__ void upk2(unsigned long long v, float& lo, float& hi) {
    asm("mov.b64 {%0, %1}, %2;" : "=f"(lo), "=f"(hi) : "l"(v));
}
__device__ __forceinline__ void fma2(unsigned long long& c, unsigned long long a,
                                     unsigned long long b) {
    asm("fma.rn.f32x2 %0, %1, %2, %0;" : "+l"(c) : "l"(a), "l"(b));
}

// ---- 128x128 tile GEMM accumulate: C += A_smem[128][lda(K)] * B_glob[K][128]
// Thread layout: 256 threads, tx = tid&15 (n), ty = tid>>4 (m). Each thread
// owns rows m0..m0+7, cols n0..n0+7 (as 4 f32x2 pairs).
template <int K>
__device__ __forceinline__ void mm_tile(const float* sA, int lda,
                                        const float* __restrict__ B,
                                        int m0, int n0,
                                        unsigned long long c[8][4]) {
#pragma unroll 2
    for (int k = 0; k < K; k += 2) {
        float2 a[8];
#pragma unroll
        for (int i = 0; i < 8; i++)
            a[i] = *reinterpret_cast<const float2*>(sA + (m0 + i) * lda + k);

        float4 b0lo = __ldg(reinterpret_cast<const float4*>(B + (size_t)k * FEAT + n0));
        float4 b0hi = __ldg(reinterpret_cast<const float4*>(B + (size_t)k * FEAT + n0 + 4));
        float4 b1lo = __ldg(reinterpret_cast<const float4*>(B + (size_t)(k + 1) * FEAT + n0));
        float4 b1hi = __ldg(reinterpret_cast<const float4*>(B + (size_t)(k + 1) * FEAT + n0 + 4));

        unsigned long long bk0[4] = {pk2(b0lo.x, b0lo.y), pk2(b0lo.z, b0lo.w),
                                     pk2(b0hi.x, b0hi.y), pk2(b0hi.z, b0hi.w)};
        unsigned long long bk1[4] = {pk2(b1lo.x, b1lo.y), pk2(b1lo.z, b1lo.w),
                                     pk2(b1hi.x, b1hi.y), pk2(b1hi.z, b1hi.w)};
#pragma unroll
        for (int i = 0; i < 8; i++) {
            unsigned long long a0 = pk2(a[i].x, a[i].x);
            unsigned long long a1 = pk2(a[i].y, a[i].y);
#pragma unroll
            for (int j = 0; j < 4; j++) {
                fma2(c[i][j], a0, bk0[j]);
                fma2(c[i][j], a1, bk1[j]);
            }
        }
    }
}

// -------------------------------------------------------------------------
// Kernel 0: g_agg = node_feats  (residual folded in)
// -------------------------------------------------------------------------
__global__ void init_agg_kernel(const float* __restrict__ node_feats, int total4) {
    int i = blockIdx.x * blockDim.x + threadIdx.x;
    int stride = gridDim.x * blockDim.x;
    const float4* src = reinterpret_cast<const float4*>(node_feats);
    float4* dst = reinterpret_cast<float4*>(g_agg);
    for (; i < total4; i += stride) dst[i] = src[i];
}

// -------------------------------------------------------------------------
// Kernel 1: per-edge message MLP + atomic scatter into g_agg
//   m = relu(cat[h_src, e] @ W1a + b1a) @ W1b + b1b ; g_agg[dst] += m
// 128 edges per block, 256 threads, 128 KB dynamic smem.
// -------------------------------------------------------------------------
extern __shared__ float dyn_smem[];

__global__ __launch_bounds__(256, 1) void edge_kernel(
    const float* __restrict__ node_feats, const float* __restrict__ edge_feats,
    const int* __restrict__ src, const int* __restrict__ dst,
    const float* __restrict__ W1a, const float* __restrict__ b1a,
    const float* __restrict__ W1b, const float* __restrict__ b1b, int n_edges) {
    __shared__ int s_src[128];
    __shared__ int s_dst[128];
    float* s_cat = dyn_smem;  // [128][256] then reused as hidden [128][128]

    const int tid = threadIdx.x;
    const int e0 = blockIdx.x * 128;
    const int rem = min(128, n_edges - e0);

    if (tid < 128) {
        int e = e0 + tid;
        if (e >= n_edges) e = n_edges - 1;
        s_src[tid] = src[e];
        s_dst[tid] = dst[e];
    }
    __syncthreads();

    // gather cat = [node_feats[src], edge_feats] into smem, row-major [128][256]
    for (int idx = tid; idx < 128 * 64; idx += 256) {
        int m = idx >> 6;   // edge row in tile
        int q = idx & 63;   // float4 chunk within 256-col row
        int er = e0 + m;
        if (er >= n_edges) er = n_edges - 1;
        float4 v;
        if (q < 32)
            v = __ldg(reinterpret_cast<const float4*>(node_feats +
                                                      (size_t)s_src[m] * FEAT + q * 4));
        else
            v = __ldg(reinterpret_cast<const float4*>(edge_feats +
                                                      (size_t)er * FEAT + (q - 32) * 4));
        *reinterpret_cast<float4*>(s_cat + m * 256 + q * 4) = v;
    }
    __syncthreads();

    const int tx = tid & 15, ty = tid >> 4;
    const int m0 = ty * 8, n0 = tx * 8;

    // ---- layer 1: hidden = relu(cat @ W1a + b1a) ----
    unsigned long long c[8][4];
#pragma unroll
    for (int i = 0; i < 8; i++)
#pragma unroll
        for (int j = 0; j < 4; j++) c[i][j] = 0ULL;

    mm_tile<256>(s_cat, 256, W1a, m0, n0, c);

    float4 blo = __ldg(reinterpret_cast<const float4*>(b1a + n0));
    float4 bhi = __ldg(reinterpret_cast<const float4*>(b1a + n0 + 4));
    float bb[8] = {blo.x, blo.y, blo.z, blo.w, bhi.x, bhi.y, bhi.z, bhi.w};

    __syncthreads();  // everyone done reading s_cat before overwrite
#pragma unroll
    for (int i = 0; i < 8; i++) {
        float r[8];
#pragma unroll
        for (int j = 0; j < 4; j++) {
            float lo, hi;
            upk2(c[i][j], lo, hi);
            r[2 * j] = fmaxf(lo + bb[2 * j], 0.0f);
            r[2 * j + 1] = fmaxf(hi + bb[2 * j + 1], 0.0f);
        }
        *reinterpret_cast<float4*>(s_cat + (m0 + i) * FEAT + n0) =
            make_float4(r[0], r[1], r[2], r[3]);
        *reinterpret_cast<float4*>(s_cat + (m0 + i) * FEAT + n0 + 4) =
            make_float4(r[4], r[5], r[6], r[7]);
    }
    __syncthreads();

    // ---- layer 2: m = hidden @ W1b + b1b, then scatter ----
    unsigned long long c2[8][4];
#pragma unroll
    for (int i = 0; i < 8; i++)
#pragma unroll
        for (int j = 0; j < 4; j++) c2[i][j] = 0ULL;

    mm_tile<128>(s_cat, 128, W1b, m0, n0, c2);

    float4 b2lo = __ldg(reinterpret_cast<const float4*>(b1b + n0));
    float4 b2hi = __ldg(reinterpret_cast<const float4*>(b1b + n0 + 4));
    float bb2[8] = {b2lo.x, b2lo.y, b2lo.z, b2lo.w, b2hi.x, b2hi.y, b2hi.z, b2hi.w};

#pragma unroll
    for (int i = 0; i < 8; i++) {
        if (m0 + i < rem) {
            int d = s_dst[m0 + i];
            float* p = g_agg + (size_t)d * FEAT + n0;
#pragma unroll
            for (int j = 0; j < 4; j++) {
                float lo, hi;
                upk2(c2[i][j], lo, hi);
                atomicAdd(p + 2 * j, lo + bb2[2 * j]);
                atomicAdd(p + 2 * j + 1, hi + bb2[2 * j + 1]);
            }
        }
    }
}

// -------------------------------------------------------------------------
// Kernel 2: out = relu(h @ W2a + b2a) @ W2b + b2b,  h = g_agg
// 128 nodes per block, 256 threads, 64 KB dynamic smem.
// -------------------------------------------------------------------------
__global__ __launch_bounds__(256, 1) void node_kernel(
    const float* __restrict__ W2a, const float* __restrict__ b2a,
    const float* __restrict__ W2b, const float* __restrict__ b2b,
    float* __restrict__ out, int n_nodes) {
    float* s_h = dyn_smem;  // [128][128]
    const int tid = threadIdx.x;
    const int v0 = blockIdx.x * 128;
    const int rem = min(128, n_nodes - v0);

    for (int idx = tid; idx < 128 * 32; idx += 256) {
        int m = idx >> 5;
        int q = idx & 31;
        int mm = (m < rem) ? m : 0;
        float4 v = *reinterpret_cast<const float4*>(g_agg + (size_t)(v0 + mm) * FEAT + q * 4);
        *reinterpret_cast<float4*>(s_h + m * FEAT + q * 4) = v;
    }
    __syncthreads();

    const int tx = tid & 15, ty = tid >> 4;
    const int m0 = ty * 8, n0 = tx * 8;

    unsigned long long c[8][4];
#pragma unroll
    for (int i = 0; i < 8; i++)
#pragma unroll
        for (int j = 0; j < 4; j++) c[i][j] = 0ULL;

    mm_tile<128>(s_h, 128, W2a, m0, n0, c);

    float4 blo = __ldg(reinterpret_cast<const float4*>(b2a + n0));
    float4 bhi = __ldg(reinterpret_cast<const float4*>(b2a + n0 + 4));
    float bb[8] = {blo.x, blo.y, blo.z, blo.w, bhi.x, bhi.y, bhi.z, bhi.w};

    __syncthreads();
#pragma unroll
    for (int i = 0; i < 8; i++) {
        float r[8];
#pragma unroll
        for (int j = 0; j < 4; j++) {
            float lo, hi;
            upk2(c[i][j], lo, hi);
            r[2 * j] = fmaxf(lo + bb[2 * j], 0.0f);
            r[2 * j + 1] = fmaxf(hi + bb[2 * j + 1], 0.0f);
        }
        *reinterpret_cast<float4*>(s_h + (m0 + i) * FEAT + n0) =
            make_float4(r[0], r[1], r[2], r[3]);
        *reinterpret_cast<float4*>(s_h + (m0 + i) * FEAT + n0 + 4) =
            make_float4(r[4], r[5], r[6], r[7]);
    }
    __syncthreads();

    unsigned long long c2[8][4];
#pragma unroll
    for (int i = 0; i < 8; i++)
#pragma unroll
        for (int j = 0; j < 4; j++) c2[i][j] = 0ULL;

    mm_tile<128>(s_h, 128, W2b, m0, n0, c2);

    float4 b2lo = __ldg(reinterpret_cast<const float4*>(b2b + n0));
    float4 b2hi = __ldg(reinterpret_cast<const float4*>(b2b + n0 + 4));
    float bb2[8] = {b2lo.x, b2lo.y, b2lo.z, b2lo.w, b2hi.x, b2hi.y, b2hi.z, b2hi.w};

#pragma unroll
    for (int i = 0; i < 8; i++) {
        if (m0 + i < rem) {
            float r[8];
#pragma unroll
            for (int j = 0; j < 4; j++) {
                float lo, hi;
                upk2(c2[i][j], lo, hi);
                r[2 * j] = lo + bb2[2 * j];
                r[2 * j + 1] = hi + bb2[2 * j + 1];
            }
            float* p = out + (size_t)(v0 + m0 + i) * FEAT + n0;
            *reinterpret_cast<float4*>(p) = make_float4(r[0], r[1], r[2], r[3]);
            *reinterpret_cast<float4*>(p + 4) = make_float4(r[4], r[5], r[6], r[7]);
        }
    }
}

// -------------------------------------------------------------------------
extern "C" void kernel_launch(void* const* d_in, const int* in_sizes, int n_in,
                              void* d_out, int out_size) {
    const float* node_feats = (const float*)d_in[0];
    const float* edge_feats = (const float*)d_in[1];
    const int* src = (const int*)d_in[2];
    const int* dst = (const int*)d_in[3];
    const float* W1a = (const float*)d_in[4];
    const float* b1a = (const float*)d_in[5];
    const float* W1b = (const float*)d_in[6];
    const float* b1b = (const float*)d_in[7];
    const float* W2a = (const float*)d_in[8];
    const float* b2a = (const float*)d_in[9];
    const float* W2b = (const float*)d_in[10];
    const float* b2b = (const float*)d_in[11];
    float* out = (float*)d_out;

    const int n_nodes = in_sizes[0] / FEAT;
    const int n_edges = in_sizes[2];

    cudaFuncSetAttribute(edge_kernel, cudaFuncAttributeMaxDynamicSharedMemorySize,
                         128 * 256 * 4);
    cudaFuncSetAttribute(node_kernel, cudaFuncAttributeMaxDynamicSharedMemorySize,
                         128 * 128 * 4);

    init_agg_kernel<<<512, 256>>>(node_feats, n_nodes * (FEAT / 4));

    int edge_blocks = (n_edges + 127) / 128;
    edge_kernel<<<edge_blocks, 256, 128 * 256 * 4>>>(node_feats, edge_feats, src, dst,
                                                     W1a, b1a, W1b, b1b, n_edges);

    int node_blocks = (n_nodes + 127) / 128;
    node_kernel<<<node_blocks, 256, 128 * 128 * 4>>>(W2a, b2a, W2b, b2b, out, n_nodes);
}

// round 4
// speedup vs baseline: 3.0017x; 3.0017x over previous
#include <cuda_runtime.h>
#include <cuda_bf16.h>

#define FEAT 128
#define MAX_NODES 50000

typedef unsigned int u32;

// ---------------- device scratch ----------------
static __device__ float g_agg[(size_t)MAX_NODES * FEAT];
// weight fragments, u32-packed per mma.m16n8k16 B-lane layout:
// idx = (((chunk*2+split)*4 + ks)*16 + nf)*64 + lane*2 + r
static __device__ u32 g_w1a_f[32768];  // K=256: 4 chunks
static __device__ u32 g_w1b_f[16384];  // K=128: 2 chunks
static __device__ u32 g_w2a_f[16384];
static __device__ u32 g_w2b_f[16384];

// smem geometry (dynamic, bytes)
#define A1_STRIDE 144   // 64 bf16 data + pad (36 words == 4 mod 32 -> conflict-free)
#define A1_TILE   (128 * A1_STRIDE)         // 18432
#define A2_STRIDE 272   // 128 bf16 data + pad (68 words == 4 mod 32)
#define A2_TILE   (128 * A2_STRIDE)         // 34816
#define SB_OFF    (2 * A2_TILE)             // 69632
#define DYN_BYTES (SB_OFF + 32768)          // 102400

// ---------------- helpers ----------------
__device__ __forceinline__ u32 smem_u32(const void* p) {
    u32 a;
    asm("{ .reg .u64 t; cvta.to.shared.u64 t, %1; cvt.u32.u64 %0, t; }" : "=r"(a) : "l"(p));
    return a;
}
__device__ __forceinline__ u32 lds32(u32 a) {
    u32 v;
    asm volatile("ld.shared.b32 %0, [%1];" : "=r"(v) : "r"(a));
    return v;
}
__device__ __forceinline__ void lds64(u32 a, u32& x, u32& y) {
    asm volatile("ld.shared.v2.b32 {%0,%1}, [%2];" : "=r"(x), "=r"(y) : "r"(a));
}
__device__ __forceinline__ void sts32(u32 a, u32 v) {
    asm volatile("st.shared.b32 [%0], %1;" ::"r"(a), "r"(v));
}
__device__ __forceinline__ void sts128(u32 a, uint4 v) {
    asm volatile("st.shared.v4.b32 [%0], {%1,%2,%3,%4};" ::"r"(a), "r"(v.x), "r"(v.y),
                 "r"(v.z), "r"(v.w));
}

__device__ __forceinline__ void mma16816(float c[4], const u32 a[4], u32 b0, u32 b1) {
    asm volatile(
        "mma.sync.aligned.m16n8k16.row.col.f32.bf16.bf16.f32 "
        "{%0,%1,%2,%3}, {%4,%5,%6,%7}, {%8,%9}, {%0,%1,%2,%3};"
        : "+f"(c[0]), "+f"(c[1]), "+f"(c[2]), "+f"(c[3])
        : "r"(a[0]), "r"(a[1]), "r"(a[2]), "r"(a[3]), "r"(b0), "r"(b1));
}

// fp32 pair -> packed bf16x2 hi + bf16x2 lo (x in low half)
__device__ __forceinline__ void split2(float x, float y, u32& h, u32& l) {
    asm("cvt.rn.bf16x2.f32 %0, %1, %2;" : "=r"(h) : "f"(y), "f"(x));
    float rx = x - __uint_as_float(h << 16);
    float ry = y - __uint_as_float(h & 0xFFFF0000u);
    asm("cvt.rn.bf16x2.f32 %0, %1, %2;" : "=r"(l) : "f"(ry), "f"(rx));
}

// convert 32 contiguous fp32 from global -> hi/lo bf16 into smem (byte addrs)
__device__ __forceinline__ void conv32(const float* __restrict__ rp, u32 dhi, u32 dlo) {
#pragma unroll
    for (int q = 0; q < 8; q++) {
        float4 f = __ldg((const float4*)rp + q);
        u32 h0, l0, h1, l1;
        split2(f.x, f.y, h0, l0);
        split2(f.z, f.w, h1, l1);
        sts32(dhi + q * 8, h0);
        sts32(dhi + q * 8 + 4, h1);
        sts32(dlo + q * 8, l0);
        sts32(dlo + q * 8 + 4, l1);
    }
}

// copy one 32KB weight-fragment chunk global -> smem
__device__ __forceinline__ void copy_w(const u32* __restrict__ g, u32 sB, int tid) {
    const uint4* s = (const uint4*)g;
#pragma unroll
    for (int i = 0; i < 8; i++) sts128(sB + (tid + i * 256) * 16, __ldg(s + tid + i * 256));
}

// one K=64 chunk of 3-split GEMM: acc[16][4] += A(16x64) * B(64x128)
__device__ __forceinline__ void gemm_chunk(u32 aHi, u32 stride, u32 loOff, u32 bB,
                                           float (*acc)[4], int lane) {
    const u32 arow = aHi + (lane >> 2) * stride + (lane & 3) * 4;
    const u32 bl = bB + lane * 8;
#pragma unroll
    for (int ks = 0; ks < 4; ks++) {
        u32 ab = arow + ks * 32;
        u32 ah[4], al[4];
        ah[0] = lds32(ab);
        ah[1] = lds32(ab + 8 * stride);
        ah[2] = lds32(ab + 16);
        ah[3] = lds32(ab + 8 * stride + 16);
        al[0] = lds32(ab + loOff);
        al[1] = lds32(ab + loOff + 8 * stride);
        al[2] = lds32(ab + loOff + 16);
        al[3] = lds32(ab + loOff + 8 * stride + 16);
        u32 bk = bl + ks * 4096;
#pragma unroll
        for (int nf = 0; nf < 16; nf++) {
            u32 bh0, bh1, bl0, bl1;
            lds64(bk + nf * 256, bh0, bh1);
            lds64(bk + nf * 256 + 16384, bl0, bl1);
            mma16816(acc[nf], ah, bh0, bh1);
            mma16816(acc[nf], ah, bl0, bl1);
            mma16816(acc[nf], al, bh0, bh1);
        }
    }
}

// ---------------- kernel 0: weight prep (split + fragment pack) ----------------
__device__ __forceinline__ int fidx(int ke, int n, int split) {
    int chunk = ke >> 6, ks = (ke >> 4) & 3, r = (ke >> 3) & 1, l4 = (ke >> 1) & 3;
    int nf = n >> 3, lane = (n & 7) * 4 + l4;
    return (((chunk * 2 + split) * 4 + ks) * 16 + nf) * 64 + lane * 2 + r;
}

__global__ void prep_weights(const float* __restrict__ W1a, const float* __restrict__ W1b,
                             const float* __restrict__ W2a, const float* __restrict__ W2b) {
    // kpair-count x 128: w1a 16384, others 8192 each
    int total = 16384 + 3 * 8192;
    for (int i = blockIdx.x * blockDim.x + threadIdx.x; i < total;
         i += gridDim.x * blockDim.x) {
        int j = i;
        const float* W;
        u32* G;
        if (j < 16384) {
            W = W1a;
            G = g_w1a_f;
        } else {
            j -= 16384;
            int ws = j / 8192;
            j %= 8192;
            W = (ws == 0) ? W1b : (ws == 1) ? W2a : W2b;
            G = (ws == 0) ? g_w1b_f : (ws == 1) ? g_w2a_f : g_w2b_f;
        }
        int ke = (j >> 7) * 2, n = j & 127;
        float x0 = W[ke * 128 + n], x1 = W[(ke + 1) * 128 + n];
        u32 H, L;
        split2(x0, x1, H, L);
        G[fidx(ke, n, 0)] = H;
        G[fidx(ke, n, 1)] = L;
    }
}

// ---------------- kernel 1: g_agg = node_feats ----------------
__global__ void init_agg_kernel(const float* __restrict__ node_feats, int total4) {
    int i = blockIdx.x * blockDim.x + threadIdx.x;
    int stride = gridDim.x * blockDim.x;
    const float4* s = (const float4*)node_feats;
    float4* d = (float4*)g_agg;
    for (; i < total4; i += stride) d[i] = s[i];
}

// ---------------- kernel 2: edge MLP + scatter ----------------
extern __shared__ char dynraw[];

__global__ __launch_bounds__(256, 2) void edge_kernel(
    const float* __restrict__ node_feats, const float* __restrict__ edge_feats,
    const int* __restrict__ src, const int* __restrict__ dst,
    const float* __restrict__ b1a, const float* __restrict__ b1b, int n_edges) {
    __shared__ int s_src[128], s_dst[128];
    __shared__ float s_ba[FEAT], s_bb[FEAT];

    const int tid = threadIdx.x;
    const int wid = tid >> 5, lane = tid & 31;
    const int m0 = wid * 16;
    const u32 smb = smem_u32(dynraw);
    const u32 sA = smb;            // layer1 per-chunk A (hi @0, lo @A1_TILE); aliased by A2
    const u32 sB = smb + SB_OFF;

    const int e0 = blockIdx.x * 128;
    if (tid < 128) {
        int e = min(e0 + tid, n_edges - 1);
        s_src[tid] = __ldg(src + e);
        s_dst[tid] = __ldg(dst + e);
        s_ba[tid] = __ldg(b1a + tid);
        s_bb[tid] = __ldg(b1b + tid);
    }
    __syncthreads();

    float acc[16][4];
#pragma unroll
    for (int i = 0; i < 16; i++)
#pragma unroll
        for (int j = 0; j < 4; j++) acc[i][j] = 0.0f;

    const int cm = tid >> 1, half = tid & 1;
    const int rr = lane >> 2, c2 = (lane & 3) * 2;

    // ---- layer 1: K=256, 4 chunks ----
    for (int c = 0; c < 4; c++) {
        copy_w(g_w1a_f + c * 8192, sB, tid);
        const float* rp;
        if (c < 2)
            rp = node_feats + (size_t)s_src[cm] * FEAT + c * 64 + half * 32;
        else
            rp = edge_feats + (size_t)min(e0 + cm, n_edges - 1) * FEAT + (c - 2) * 64 +
                 half * 32;
        u32 d = sA + cm * A1_STRIDE + half * 64;
        conv32(rp, d, d + A1_TILE);
        __syncthreads();
        gemm_chunk(sA + m0 * A1_STRIDE, A1_STRIDE, A1_TILE, sB, acc, lane);
        __syncthreads();
    }

    // ---- epilogue 1: relu(acc + b1a) -> A2 tiles (aliases A1 region) ----
#pragma unroll
    for (int nf = 0; nf < 16; nf++) {
        int n0 = nf * 8 + c2;
        float v0 = fmaxf(acc[nf][0] + s_ba[n0], 0.0f);
        float v1 = fmaxf(acc[nf][1] + s_ba[n0 + 1], 0.0f);
        float v2 = fmaxf(acc[nf][2] + s_ba[n0], 0.0f);
        float v3 = fmaxf(acc[nf][3] + s_ba[n0 + 1], 0.0f);
        u32 h, l;
        u32 ad = sA + (m0 + rr) * A2_STRIDE + nf * 16 + (lane & 3) * 4;
        split2(v0, v1, h, l);
        sts32(ad, h);
        sts32(ad + A2_TILE, l);
        split2(v2, v3, h, l);
        sts32(ad + 8 * A2_STRIDE, h);
        sts32(ad + 8 * A2_STRIDE + A2_TILE, l);
        acc[nf][0] = acc[nf][1] = acc[nf][2] = acc[nf][3] = 0.0f;
    }
    __syncthreads();

    // ---- layer 2: K=128, 2 chunks ----
    for (int c = 0; c < 2; c++) {
        copy_w(g_w1b_f + c * 8192, sB, tid);
        __syncthreads();
        gemm_chunk(sA + m0 * A2_STRIDE + c * 128, A2_STRIDE, A2_TILE, sB, acc, lane);
        __syncthreads();
    }

    // ---- epilogue 2: scatter (acc + b1b) into g_agg ----
    const int r0 = m0 + rr, r1 = r0 + 8;
    const bool ok0 = (e0 + r0 < n_edges), ok1 = (e0 + r1 < n_edges);
    float* p0 = g_agg + (size_t)s_dst[r0] * FEAT;
    float* p1 = g_agg + (size_t)s_dst[r1] * FEAT;
#pragma unroll
    for (int nf = 0; nf < 16; nf++) {
        int n0 = nf * 8 + c2;
        if (ok0) {
            atomicAdd(p0 + n0, acc[nf][0] + s_bb[n0]);
            atomicAdd(p0 + n0 + 1, acc[nf][1] + s_bb[n0 + 1]);
        }
        if (ok1) {
            atomicAdd(p1 + n0, acc[nf][2] + s_bb[n0]);
            atomicAdd(p1 + n0 + 1, acc[nf][3] + s_bb[n0 + 1]);
        }
    }
}

// ---------------- kernel 3: node MLP ----------------
__global__ __launch_bounds__(256, 2) void node_kernel(const float* __restrict__ b2a,
                                                      const float* __restrict__ b2b,
                                                      float* __restrict__ out, int n_nodes) {
    __shared__ float s_ba[FEAT], s_bb[FEAT];

    const int tid = threadIdx.x;
    const int wid = tid >> 5, lane = tid & 31;
    const int m0 = wid * 16;
    const u32 smb = smem_u32(dynraw);
    const u32 sA = smb;
    const u32 sB = smb + SB_OFF;

    const int v0 = blockIdx.x * 128;
    if (tid < 128) {
        s_ba[tid] = __ldg(b2a + tid);
        s_bb[tid] = __ldg(b2b + tid);
    }

    // convert h = g_agg rows into A2 layout (full K=128 at once)
    const int cm = tid >> 1, half = tid & 1;
    {
        const float* rp =
            g_agg + (size_t)min(v0 + cm, n_nodes - 1) * FEAT + half * 64;
        u32 d = sA + cm * A2_STRIDE + half * 128;
        conv32(rp, d, d + A2_TILE);
        conv32(rp + 32, d + 64, d + 64 + A2_TILE);
    }
    __syncthreads();

    float acc[16][4];
#pragma unroll
    for (int i = 0; i < 16; i++)
#pragma unroll
        for (int j = 0; j < 4; j++) acc[i][j] = 0.0f;

    const int rr = lane >> 2, c2 = (lane & 3) * 2;

    // ---- layer 1: h @ W2a ----
    for (int c = 0; c < 2; c++) {
        copy_w(g_w2a_f + c * 8192, sB, tid);
        __syncthreads();
        gemm_chunk(sA + m0 * A2_STRIDE + c * 128, A2_STRIDE, A2_TILE, sB, acc, lane);
        __syncthreads();
    }

    // ---- epilogue 1: relu -> A2 (overwrite input; all reads done) ----
#pragma unroll
    for (int nf = 0; nf < 16; nf++) {
        int n0 = nf * 8 + c2;
        float v0f = fmaxf(acc[nf][0] + s_ba[n0], 0.0f);
        float v1f = fmaxf(acc[nf][1] + s_ba[n0 + 1], 0.0f);
        float v2f = fmaxf(acc[nf][2] + s_ba[n0], 0.0f);
        float v3f = fmaxf(acc[nf][3] + s_ba[n0 + 1], 0.0f);
        u32 h, l;
        u32 ad = sA + (m0 + rr) * A2_STRIDE + nf * 16 + (lane & 3) * 4;
        split2(v0f, v1f, h, l);
        sts32(ad, h);
        sts32(ad + A2_TILE, l);
        split2(v2f, v3f, h, l);
        sts32(ad + 8 * A2_STRIDE, h);
        sts32(ad + 8 * A2_STRIDE + A2_TILE, l);
        acc[nf][0] = acc[nf][1] = acc[nf][2] = acc[nf][3] = 0.0f;
    }
    __syncthreads();

    // ---- layer 2: hidden @ W2b ----
    for (int c = 0; c < 2; c++) {
        copy_w(g_w2b_f + c * 8192, sB, tid);
        __syncthreads();
        gemm_chunk(sA + m0 * A2_STRIDE + c * 128, A2_STRIDE, A2_TILE, sB, acc, lane);
        __syncthreads();
    }

    // ---- epilogue 2: out = acc + b2b ----
    const int r0 = m0 + rr, r1 = r0 + 8;
#pragma unroll
    for (int nf = 0; nf < 16; nf++) {
        int n0 = nf * 8 + c2;
        if (v0 + r0 < n_nodes) {
            float2 v = make_float2(acc[nf][0] + s_bb[n0], acc[nf][1] + s_bb[n0 + 1]);
            *(float2*)(out + (size_t)(v0 + r0) * FEAT + n0) = v;
        }
        if (v0 + r1 < n_nodes) {
            float2 v = make_float2(acc[nf][2] + s_bb[n0], acc[nf][3] + s_bb[n0 + 1]);
            *(float2*)(out + (size_t)(v0 + r1) * FEAT + n0) = v;
        }
    }
}

// ---------------- launch ----------------
extern "C" void kernel_launch(void* const* d_in, const int* in_sizes, int n_in,
                              void* d_out, int out_size) {
    const float* node_feats = (const float*)d_in[0];
    const float* edge_feats = (const float*)d_in[1];
    const int* src = (const int*)d_in[2];
    const int* dst = (const int*)d_in[3];
    const float* W1a = (const float*)d_in[4];
    const float* b1a = (const float*)d_in[5];
    const float* W1b = (const float*)d_in[6];
    const float* b1b = (const float*)d_in[7];
    const float* W2a = (const float*)d_in[8];
    const float* b2a = (const float*)d_in[9];
    const float* W2b = (const float*)d_in[10];
    const float* b2b = (const float*)d_in[11];
    float* out = (float*)d_out;

    const int n_nodes = in_sizes[0] / FEAT;
    const int n_edges = in_sizes[2];

    cudaFuncSetAttribute(edge_kernel, cudaFuncAttributeMaxDynamicSharedMemorySize,
                         DYN_BYTES);
    cudaFuncSetAttribute(node_kernel, cudaFuncAttributeMaxDynamicSharedMemorySize,
                         DYN_BYTES);

    prep_weights<<<160, 256>>>(W1a, W1b, W2a, W2b);
    init_agg_kernel<<<512, 256>>>(node_feats, n_nodes * (FEAT / 4));

    int edge_blocks = (n_edges + 127) / 128;
    edge_kernel<<<edge_blocks, 256, DYN_BYTES>>>(node_feats, edge_feats, src, dst, b1a,
                                                 b1b, n_edges);

    int node_blocks = (n_nodes + 127) / 128;
    node_kernel<<<node_blocks, 256, DYN_BYTES>>>(b2a, b2b, out, n_nodes);
}

// round 5
// speedup vs baseline: 3.0076x; 1.0020x over previous
#include <cuda_runtime.h>
#include <cuda_bf16.h>

#define FEAT 128
#define MAX_NODES 50000

typedef unsigned int u32;

// ---------------- device scratch ----------------
static __device__ float g_agg[(size_t)MAX_NODES * FEAT];
// weight fragments, u32-packed per mma.m16n8k16 B-lane layout:
// idx = (((chunk*2+split)*4 + ks)*16 + nf)*64 + lane*2 + r
static __device__ u32 g_w1a_f[32768];  // K=256: 4 chunks
static __device__ u32 g_w1b_f[16384];  // K=128: 2 chunks
static __device__ u32 g_w2a_f[16384];
static __device__ u32 g_w2b_f[16384];

// smem geometry (dynamic, bytes)
#define A1_STRIDE 144   // 64 bf16 data + pad (36 words == 4 mod 32 -> conflict-free)
#define A1_TILE   (128 * A1_STRIDE)         // 18432
#define A2_STRIDE 272   // 128 bf16 data + pad (68 words == 4 mod 32)
#define A2_TILE   (128 * A2_STRIDE)         // 34816
#define SB_OFF    (2 * A2_TILE)             // 69632
#define DYN_BYTES (SB_OFF + 32768)          // 102400

// ---------------- helpers ----------------
__device__ __forceinline__ u32 smem_u32(const void* p) {
    u32 a;
    asm("{ .reg .u64 t; cvta.to.shared.u64 t, %1; cvt.u32.u64 %0, t; }" : "=r"(a) : "l"(p));
    return a;
}
__device__ __forceinline__ u32 lds32(u32 a) {
    u32 v;
    asm volatile("ld.shared.b32 %0, [%1];" : "=r"(v) : "r"(a));
    return v;
}
__device__ __forceinline__ void lds64(u32 a, u32& x, u32& y) {
    asm volatile("ld.shared.v2.b32 {%0,%1}, [%2];" : "=r"(x), "=r"(y) : "r"(a));
}
__device__ __forceinline__ void sts32(u32 a, u32 v) {
    asm volatile("st.shared.b32 [%0], %1;" ::"r"(a), "r"(v));
}
__device__ __forceinline__ void sts128(u32 a, uint4 v) {
    asm volatile("st.shared.v4.b32 [%0], {%1,%2,%3,%4};" ::"r"(a), "r"(v.x), "r"(v.y),
                 "r"(v.z), "r"(v.w));
}

__device__ __forceinline__ void mma16816(float c[4], const u32 a[4], u32 b0, u32 b1) {
    asm volatile(
        "mma.sync.aligned.m16n8k16.row.col.f32.bf16.bf16.f32 "
        "{%0,%1,%2,%3}, {%4,%5,%6,%7}, {%8,%9}, {%0,%1,%2,%3};"
        : "+f"(c[0]), "+f"(c[1]), "+f"(c[2]), "+f"(c[3])
        : "r"(a[0]), "r"(a[1]), "r"(a[2]), "r"(a[3]), "r"(b0), "r"(b1));
}

// fp32 pair -> packed bf16x2 hi + bf16x2 lo (x in low half)
__device__ __forceinline__ void split2(float x, float y, u32& h, u32& l) {
    asm("cvt.rn.bf16x2.f32 %0, %1, %2;" : "=r"(h) : "f"(y), "f"(x));
    float rx = x - __uint_as_float(h << 16);
    float ry = y - __uint_as_float(h & 0xFFFF0000u);
    asm("cvt.rn.bf16x2.f32 %0, %1, %2;" : "=r"(l) : "f"(ry), "f"(rx));
}

// convert 32 contiguous fp32 from global -> hi/lo bf16 into smem (byte addrs)
__device__ __forceinline__ void conv32(const float* __restrict__ rp, u32 dhi, u32 dlo) {
#pragma unroll
    for (int q = 0; q < 8; q++) {
        float4 f = __ldg((const float4*)rp + q);
        u32 h0, l0, h1, l1;
        split2(f.x, f.y, h0, l0);
        split2(f.z, f.w, h1, l1);
        sts32(dhi + q * 8, h0);
        sts32(dhi + q * 8 + 4, h1);
        sts32(dlo + q * 8, l0);
        sts32(dlo + q * 8 + 4, l1);
    }
}

// copy one 32KB weight-fragment chunk global -> smem
__device__ __forceinline__ void copy_w(const u32* __restrict__ g, u32 sB, int tid) {
    const uint4* s = (const uint4*)g;
#pragma unroll
    for (int i = 0; i < 8; i++) sts128(sB + (tid + i * 256) * 16, __ldg(s + tid + i * 256));
}

// one K=64 chunk of 3-split GEMM: acc[16][4] += A(16x64) * B(64x128)
__device__ __forceinline__ void gemm_chunk(u32 aHi, u32 stride, u32 loOff, u32 bB,
                                           float (*acc)[4], int lane) {
    const u32 arow = aHi + (lane >> 2) * stride + (lane & 3) * 4;
    const u32 bl = bB + lane * 8;
#pragma unroll
    for (int ks = 0; ks < 4; ks++) {
        u32 ab = arow + ks * 32;
        u32 ah[4], al[4];
        ah[0] = lds32(ab);
        ah[1] = lds32(ab + 8 * stride);
        ah[2] = lds32(ab + 16);
        ah[3] = lds32(ab + 8 * stride + 16);
        al[0] = lds32(ab + loOff);
        al[1] = lds32(ab + loOff + 8 * stride);
        al[2] = lds32(ab + loOff + 16);
        al[3] = lds32(ab + loOff + 8 * stride + 16);
        u32 bk = bl + ks * 4096;
#pragma unroll
        for (int nf = 0; nf < 16; nf++) {
            u32 bh0, bh1, bl0, bl1;
            lds64(bk + nf * 256, bh0, bh1);
            lds64(bk + nf * 256 + 16384, bl0, bl1);
            mma16816(acc[nf], ah, bh0, bh1);
            mma16816(acc[nf], ah, bl0, bl1);
            mma16816(acc[nf], al, bh0, bh1);
        }
    }
}

// ---------------- kernel 0: weight prep (split + fragment pack) ----------------
__device__ __forceinline__ int fidx(int ke, int n, int split) {
    int chunk = ke >> 6, ks = (ke >> 4) & 3, r = (ke >> 3) & 1, l4 = (ke >> 1) & 3;
    int nf = n >> 3, lane = (n & 7) * 4 + l4;
    return (((chunk * 2 + split) * 4 + ks) * 16 + nf) * 64 + lane * 2 + r;
}

__global__ void prep_weights(const float* __restrict__ W1a, const float* __restrict__ W1b,
                             const float* __restrict__ W2a, const float* __restrict__ W2b) {
    // kpair-count x 128: w1a 16384, others 8192 each
    int total = 16384 + 3 * 8192;
    for (int i = blockIdx.x * blockDim.x + threadIdx.x; i < total;
         i += gridDim.x * blockDim.x) {
        int j = i;
        const float* W;
        u32* G;
        if (j < 16384) {
            W = W1a;
            G = g_w1a_f;
        } else {
            j -= 16384;
            int ws = j / 8192;
            j %= 8192;
            W = (ws == 0) ? W1b : (ws == 1) ? W2a : W2b;
            G = (ws == 0) ? g_w1b_f : (ws == 1) ? g_w2a_f : g_w2b_f;
        }
        int ke = (j >> 7) * 2, n = j & 127;
        float x0 = W[ke * 128 + n], x1 = W[(ke + 1) * 128 + n];
        u32 H, L;
        split2(x0, x1, H, L);
        G[fidx(ke, n, 0)] = H;
        G[fidx(ke, n, 1)] = L;
    }
}

// ---------------- kernel 1: g_agg = node_feats ----------------
__global__ void init_agg_kernel(const float* __restrict__ node_feats, int total4) {
    int i = blockIdx.x * blockDim.x + threadIdx.x;
    int stride = gridDim.x * blockDim.x;
    const float4* s = (const float4*)node_feats;
    float4* d = (float4*)g_agg;
    for (; i < total4; i += stride) d[i] = s[i];
}

// ---------------- kernel 2: edge MLP + scatter ----------------
extern __shared__ char dynraw[];

__global__ __launch_bounds__(256, 2) void edge_kernel(
    const float* __restrict__ node_feats, const float* __restrict__ edge_feats,
    const int* __restrict__ src, const int* __restrict__ dst,
    const float* __restrict__ b1a, const float* __restrict__ b1b, int n_edges) {
    __shared__ int s_src[128], s_dst[128];
    __shared__ float s_ba[FEAT], s_bb[FEAT];

    const int tid = threadIdx.x;
    const int wid = tid >> 5, lane = tid & 31;
    const int m0 = wid * 16;
    const u32 smb = smem_u32(dynraw);
    const u32 sA = smb;            // layer1 per-chunk A (hi @0, lo @A1_TILE); aliased by A2
    const u32 sB = smb + SB_OFF;

    const int e0 = blockIdx.x * 128;
    if (tid < 128) {
        int e = min(e0 + tid, n_edges - 1);
        s_src[tid] = __ldg(src + e);
        s_dst[tid] = __ldg(dst + e);
        s_ba[tid] = __ldg(b1a + tid);
        s_bb[tid] = __ldg(b1b + tid);
    }
    __syncthreads();

    float acc[16][4];
#pragma unroll
    for (int i = 0; i < 16; i++)
#pragma unroll
        for (int j = 0; j < 4; j++) acc[i][j] = 0.0f;

    const int cm = tid >> 1, half = tid & 1;
    const int rr = lane >> 2, c2 = (lane & 3) * 2;

    // ---- layer 1: K=256, 4 chunks ----
    for (int c = 0; c < 4; c++) {
        copy_w(g_w1a_f + c * 8192, sB, tid);
        const float* rp;
        if (c < 2)
            rp = node_feats + (size_t)s_src[cm] * FEAT + c * 64 + half * 32;
        else
            rp = edge_feats + (size_t)min(e0 + cm, n_edges - 1) * FEAT + (c - 2) * 64 +
                 half * 32;
        u32 d = sA + cm * A1_STRIDE + half * 64;
        conv32(rp, d, d + A1_TILE);
        __syncthreads();
        gemm_chunk(sA + m0 * A1_STRIDE, A1_STRIDE, A1_TILE, sB, acc, lane);
        __syncthreads();
    }

    // ---- epilogue 1: relu(acc + b1a) -> A2 tiles (aliases A1 region) ----
#pragma unroll
    for (int nf = 0; nf < 16; nf++) {
        int n0 = nf * 8 + c2;
        float v0 = fmaxf(acc[nf][0] + s_ba[n0], 0.0f);
        float v1 = fmaxf(acc[nf][1] + s_ba[n0 + 1], 0.0f);
        float v2 = fmaxf(acc[nf][2] + s_ba[n0], 0.0f);
        float v3 = fmaxf(acc[nf][3] + s_ba[n0 + 1], 0.0f);
        u32 h, l;
        u32 ad = sA + (m0 + rr) * A2_STRIDE + nf * 16 + (lane & 3) * 4;
        split2(v0, v1, h, l);
        sts32(ad, h);
        sts32(ad + A2_TILE, l);
        split2(v2, v3, h, l);
        sts32(ad + 8 * A2_STRIDE, h);
        sts32(ad + 8 * A2_STRIDE + A2_TILE, l);
        acc[nf][0] = acc[nf][1] = acc[nf][2] = acc[nf][3] = 0.0f;
    }
    __syncthreads();

    // ---- layer 2: K=128, 2 chunks ----
    for (int c = 0; c < 2; c++) {
        copy_w(g_w1b_f + c * 8192, sB, tid);
        __syncthreads();
        gemm_chunk(sA + m0 * A2_STRIDE + c * 128, A2_STRIDE, A2_TILE, sB, acc, lane);
        __syncthreads();
    }

    // ---- epilogue 2: scatter (acc + b1b) into g_agg ----
    const int r0 = m0 + rr, r1 = r0 + 8;
    const bool ok0 = (e0 + r0 < n_edges), ok1 = (e0 + r1 < n_edges);
    float* p0 = g_agg + (size_t)s_dst[r0] * FEAT;
    float* p1 = g_agg + (size_t)s_dst[r1] * FEAT;
#pragma unroll
    for (int nf = 0; nf < 16; nf++) {
        int n0 = nf * 8 + c2;
        if (ok0) {
            atomicAdd(p0 + n0, acc[nf][0] + s_bb[n0]);
            atomicAdd(p0 + n0 + 1, acc[nf][1] + s_bb[n0 + 1]);
        }
        if (ok1) {
            atomicAdd(p1 + n0, acc[nf][2] + s_bb[n0]);
            atomicAdd(p1 + n0 + 1, acc[nf][3] + s_bb[n0 + 1]);
        }
    }
}

// ---------------- kernel 3: node MLP ----------------
__global__ __launch_bounds__(256, 2) void node_kernel(const float* __restrict__ b2a,
                                                      const float* __restrict__ b2b,
                                                      float* __restrict__ out, int n_nodes) {
    __shared__ float s_ba[FEAT], s_bb[FEAT];

    const int tid = threadIdx.x;
    const int wid = tid >> 5, lane = tid & 31;
    const int m0 = wid * 16;
    const u32 smb = smem_u32(dynraw);
    const u32 sA = smb;
    const u32 sB = smb + SB_OFF;

    const int v0 = blockIdx.x * 128;
    if (tid < 128) {
        s_ba[tid] = __ldg(b2a + tid);
        s_bb[tid] = __ldg(b2b + tid);
    }

    // convert h = g_agg rows into A2 layout (full K=128 at once)
    const int cm = tid >> 1, half = tid & 1;
    {
        const float* rp =
            g_agg + (size_t)min(v0 + cm, n_nodes - 1) * FEAT + half * 64;
        u32 d = sA + cm * A2_STRIDE + half * 128;
        conv32(rp, d, d + A2_TILE);
        conv32(rp + 32, d + 64, d + 64 + A2_TILE);
    }
    __syncthreads();

    float acc[16][4];
#pragma unroll
    for (int i = 0; i < 16; i++)
#pragma unroll
        for (int j = 0; j < 4; j++) acc[i][j] = 0.0f;

    const int rr = lane >> 2, c2 = (lane & 3) * 2;

    // ---- layer 1: h @ W2a ----
    for (int c = 0; c < 2; c++) {
        copy_w(g_w2a_f + c * 8192, sB, tid);
        __syncthreads();
        gemm_chunk(sA + m0 * A2_STRIDE + c * 128, A2_STRIDE, A2_TILE, sB, acc, lane);
        __syncthreads();
    }

    // ---- epilogue 1: relu -> A2 (overwrite input; all reads done) ----
#pragma unroll
    for (int nf = 0; nf < 16; nf++) {
        int n0 = nf * 8 + c2;
        float v0f = fmaxf(acc[nf][0] + s_ba[n0], 0.0f);
        float v1f = fmaxf(acc[nf][1] + s_ba[n0 + 1], 0.0f);
        float v2f = fmaxf(acc[nf][2] + s_ba[n0], 0.0f);
        float v3f = fmaxf(acc[nf][3] + s_ba[n0 + 1], 0.0f);
        u32 h, l;
        u32 ad = sA + (m0 + rr) * A2_STRIDE + nf * 16 + (lane & 3) * 4;
        split2(v0f, v1f, h, l);
        sts32(ad, h);
        sts32(ad + A2_TILE, l);
        split2(v2f, v3f, h, l);
        sts32(ad + 8 * A2_STRIDE, h);
        sts32(ad + 8 * A2_STRIDE + A2_TILE, l);
        acc[nf][0] = acc[nf][1] = acc[nf][2] = acc[nf][3] = 0.0f;
    }
    __syncthreads();

    // ---- layer 2: hidden @ W2b ----
    for (int c = 0; c < 2; c++) {
        copy_w(g_w2b_f + c * 8192, sB, tid);
        __syncthreads();
        gemm_chunk(sA + m0 * A2_STRIDE + c * 128, A2_STRIDE, A2_TILE, sB, acc, lane);
        __syncthreads();
    }

    // ---- epilogue 2: out = acc + b2b ----
    const int r0 = m0 + rr, r1 = r0 + 8;
#pragma unroll
    for (int nf = 0; nf < 16; nf++) {
        int n0 = nf * 8 + c2;
        if (v0 + r0 < n_nodes) {
            float2 v = make_float2(acc[nf][0] + s_bb[n0], acc[nf][1] + s_bb[n0 + 1]);
            *(float2*)(out + (size_t)(v0 + r0) * FEAT + n0) = v;
        }
        if (v0 + r1 < n_nodes) {
            float2 v = make_float2(acc[nf][2] + s_bb[n0], acc[nf][3] + s_bb[n0 + 1]);
            *(float2*)(out + (size_t)(v0 + r1) * FEAT + n0) = v;
        }
    }
}

// ---------------- launch ----------------
extern "C" void kernel_launch(void* const* d_in, const int* in_sizes, int n_in,
                              void* d_out, int out_size) {
    const float* node_feats = (const float*)d_in[0];
    const float* edge_feats = (const float*)d_in[1];
    const int* src = (const int*)d_in[2];
    const int* dst = (const int*)d_in[3];
    const float* W1a = (const float*)d_in[4];
    const float* b1a = (const float*)d_in[5];
    const float* W1b = (const float*)d_in[6];
    const float* b1b = (const float*)d_in[7];
    const float* W2a = (const float*)d_in[8];
    const float* b2a = (const float*)d_in[9];
    const float* W2b = (const float*)d_in[10];
    const float* b2b = (const float*)d_in[11];
    float* out = (float*)d_out;

    const int n_nodes = in_sizes[0] / FEAT;
    const int n_edges = in_sizes[2];

    cudaFuncSetAttribute(edge_kernel, cudaFuncAttributeMaxDynamicSharedMemorySize,
                         DYN_BYTES);
    cudaFuncSetAttribute(node_kernel, cudaFuncAttributeMaxDynamicSharedMemorySize,
                         DYN_BYTES);

    prep_weights<<<160, 256>>>(W1a, W1b, W2a, W2b);
    init_agg_kernel<<<512, 256>>>(node_feats, n_nodes * (FEAT / 4));

    int edge_blocks = (n_edges + 127) / 128;
    edge_kernel<<<edge_blocks, 256, DYN_BYTES>>>(node_feats, edge_feats, src, dst, b1a,
                                                 b1b, n_edges);

    int node_blocks = (n_nodes + 127) / 128;
    node_kernel<<<node_blocks, 256, DYN_BYTES>>>(b2a, b2b, out, n_nodes);
}

// round 6
// speedup vs baseline: 3.3483x; 1.1133x over previous
#include <cuda_runtime.h>
#include <cuda_bf16.h>

#define FEAT 128
#define MAX_NODES 50000

typedef unsigned int u32;

// ---------------- device scratch ----------------
static __device__ float g_agg[(size_t)MAX_NODES * FEAT];
// weight fragments, u32-packed per mma.m16n8k16 B-lane layout:
// idx = (((chunk*2+split)*4 + ks)*16 + nf)*64 + lane*2 + r
static __device__ __align__(16) u32 g_w1a_f[32768];  // K=256: 4 chunks
static __device__ __align__(16) u32 g_w1b_f[16384];  // K=128: 2 chunks
static __device__ __align__(16) u32 g_w2a_f[16384];
static __device__ __align__(16) u32 g_w2b_f[16384];

// ---- smem geometry (dynamic, bytes) ----
// region 0 (64KB): hidden fragments (4 warps x 16KB); layer1 A tiles alias it.
//   A1 hi tile at 0 (128 rows x 144B), A1 lo tile at 18432.
// region 1 (32KB): weight fragment chunk.
#define A1_STRIDE 144
#define A1_TILEB  (128 * A1_STRIDE)   // 18432
#define HF_BYTES  65536               // 4 warps * 2mt * 2split * 8kg * 512B
#define SB_OFF    HF_BYTES            // 65536
#define DYN_BYTES (SB_OFF + 32768)    // 98304

// ---------------- helpers ----------------
__device__ __forceinline__ u32 smem_u32(const void* p) {
    u32 a;
    asm("{ .reg .u64 t; cvta.to.shared.u64 t, %1; cvt.u32.u64 %0, t; }" : "=r"(a) : "l"(p));
    return a;
}
__device__ __forceinline__ u32 lds32(u32 a) {
    u32 v;
    asm volatile("ld.shared.b32 %0, [%1];" : "=r"(v) : "r"(a));
    return v;
}
__device__ __forceinline__ void lds64(u32 a, u32& x, u32& y) {
    asm volatile("ld.shared.v2.b32 {%0,%1}, [%2];" : "=r"(x), "=r"(y) : "r"(a));
}
__device__ __forceinline__ void lds128(u32 a, u32* r) {
    asm volatile("ld.shared.v4.b32 {%0,%1,%2,%3}, [%4];"
                 : "=r"(r[0]), "=r"(r[1]), "=r"(r[2]), "=r"(r[3]) : "r"(a));
}
__device__ __forceinline__ void sts32(u32 a, u32 v) {
    asm volatile("st.shared.b32 [%0], %1;" ::"r"(a), "r"(v));
}
__device__ __forceinline__ void sts64(u32 a, u32 x, u32 y) {
    asm volatile("st.shared.v2.b32 [%0], {%1,%2};" ::"r"(a), "r"(x), "r"(y));
}

__device__ __forceinline__ void mma16816(float c[4], const u32 a[4], u32 b0, u32 b1) {
    asm volatile(
        "mma.sync.aligned.m16n8k16.row.col.f32.bf16.bf16.f32 "
        "{%0,%1,%2,%3}, {%4,%5,%6,%7}, {%8,%9}, {%0,%1,%2,%3};"
        : "+f"(c[0]), "+f"(c[1]), "+f"(c[2]), "+f"(c[3])
        : "r"(a[0]), "r"(a[1]), "r"(a[2]), "r"(a[3]), "r"(b0), "r"(b1));
}

// fp32 pair -> packed bf16x2 hi + bf16x2 lo (x in low half)
__device__ __forceinline__ void split2(float x, float y, u32& h, u32& l) {
    asm("cvt.rn.bf16x2.f32 %0, %1, %2;" : "=r"(h) : "f"(y), "f"(x));
    float rx = x - __uint_as_float(h << 16);
    float ry = y - __uint_as_float(h & 0xFFFF0000u);
    asm("cvt.rn.bf16x2.f32 %0, %1, %2;" : "=r"(l) : "f"(ry), "f"(rx));
}

// convert 32 contiguous fp32 from global -> hi/lo bf16 into smem (byte addrs)
__device__ __forceinline__ void conv32(const float* __restrict__ rp, u32 dhi, u32 dlo) {
#pragma unroll
    for (int q = 0; q < 8; q++) {
        float4 f = __ldg((const float4*)rp + q);
        u32 h0, l0, h1, l1;
        split2(f.x, f.y, h0, l0);
        split2(f.z, f.w, h1, l1);
        sts32(dhi + q * 8, h0);
        sts32(dhi + q * 8 + 4, h1);
        sts32(dlo + q * 8, l0);
        sts32(dlo + q * 8 + 4, l1);
    }
}

// async-copy one 32KB weight-fragment chunk global -> smem (128 threads)
__device__ __forceinline__ void cp_w(const u32* __restrict__ g, u32 sB, int tid) {
#pragma unroll
    for (int i = 0; i < 16; i++) {
        u32 d = sB + (u32)(tid + i * 128) * 16;
        const u32* s = g + (tid + i * 128) * 4;
        asm volatile("cp.async.cg.shared.global [%0], [%1], 16;" ::"r"(d), "l"(s));
    }
    asm volatile("cp.async.commit_group;");
}
#define CP_WAIT() asm volatile("cp.async.wait_group 0;" ::: "memory")

// ---- layer-1 GEMM chunk: acc[2][16][4] += A(32x64) * B(64x128), A in padded tile
__device__ __forceinline__ void gemm1(u32 aBase, u32 bB, float (*acc)[16][4], int lane) {
    const u32 arow = aBase + (u32)(lane >> 2) * A1_STRIDE + (lane & 3) * 4;
    const u32 bl = bB + lane * 8;
#pragma unroll
    for (int ks = 0; ks < 4; ks++) {
        u32 a[2][2][4];
#pragma unroll
        for (int mt = 0; mt < 2; mt++) {
            u32 ab = arow + mt * 16 * A1_STRIDE + ks * 32;
            a[mt][0][0] = lds32(ab);
            a[mt][0][1] = lds32(ab + 8 * A1_STRIDE);
            a[mt][0][2] = lds32(ab + 16);
            a[mt][0][3] = lds32(ab + 8 * A1_STRIDE + 16);
            u32 al = ab + A1_TILEB;
            a[mt][1][0] = lds32(al);
            a[mt][1][1] = lds32(al + 8 * A1_STRIDE);
            a[mt][1][2] = lds32(al + 16);
            a[mt][1][3] = lds32(al + 8 * A1_STRIDE + 16);
        }
        u32 bk = bl + ks * 4096;
#pragma unroll
        for (int nf = 0; nf < 16; nf++) {
            u32 bh0, bh1, bl0, bl1;
            lds64(bk + nf * 256, bh0, bh1);
            lds64(bk + nf * 256 + 16384, bl0, bl1);
#pragma unroll
            for (int mt = 0; mt < 2; mt++) {
                mma16816(acc[mt][nf], a[mt][0], bh0, bh1);
                mma16816(acc[mt][nf], a[mt][0], bl0, bl1);
                mma16816(acc[mt][nf], a[mt][1], bh0, bh1);
            }
        }
    }
}

// ---- layer-2 GEMM chunk: A read from hidden fragments (conflict-free LDS.128)
// hfrag addr: wbase + ((mt*2+split)*8 + kg)*512 + lane*16
__device__ __forceinline__ void gemm2(u32 wbase, u32 bB, float (*acc)[16][4], int lane,
                                      int kg0) {
    const u32 bl = bB + lane * 8;
#pragma unroll
    for (int ks = 0; ks < 4; ks++) {
        int kg = kg0 + ks;
        u32 a[2][2][4];
#pragma unroll
        for (int mt = 0; mt < 2; mt++) {
            lds128(wbase + (u32)((mt * 2 + 0) * 8 + kg) * 512 + lane * 16, a[mt][0]);
            lds128(wbase + (u32)((mt * 2 + 1) * 8 + kg) * 512 + lane * 16, a[mt][1]);
        }
        u32 bk = bl + ks * 4096;
#pragma unroll
        for (int nf = 0; nf < 16; nf++) {
            u32 bh0, bh1, bl0, bl1;
            lds64(bk + nf * 256, bh0, bh1);
            lds64(bk + nf * 256 + 16384, bl0, bl1);
#pragma unroll
            for (int mt = 0; mt < 2; mt++) {
                mma16816(acc[mt][nf], a[mt][0], bh0, bh1);
                mma16816(acc[mt][nf], a[mt][0], bl0, bl1);
                mma16816(acc[mt][nf], a[mt][1], bh0, bh1);
            }
        }
    }
}

// epilogue: relu(acc + bias) -> hidden fragments; zero acc
__device__ __forceinline__ void epi_to_hfrag(float (*acc)[16][4], const float* bias,
                                             u32 wbase, int lane) {
    const int c2 = (lane & 3) * 2;
#pragma unroll
    for (int mt = 0; mt < 2; mt++)
#pragma unroll
        for (int nf = 0; nf < 16; nf++) {
            int n0 = nf * 8 + c2;
            float v0 = fmaxf(acc[mt][nf][0] + bias[n0], 0.0f);
            float v1 = fmaxf(acc[mt][nf][1] + bias[n0 + 1], 0.0f);
            float v2 = fmaxf(acc[mt][nf][2] + bias[n0], 0.0f);
            float v3 = fmaxf(acc[mt][nf][3] + bias[n0 + 1], 0.0f);
            u32 h0, l0, h1, l1;
            split2(v0, v1, h0, l0);
            split2(v2, v3, h1, l1);
            int kg = nf >> 1, half = nf & 1;
            u32 ah = wbase + (u32)((mt * 2 + 0) * 8 + kg) * 512 + lane * 16 + half * 8;
            u32 al = wbase + (u32)((mt * 2 + 1) * 8 + kg) * 512 + lane * 16 + half * 8;
            sts64(ah, h0, h1);
            sts64(al, l0, l1);
            acc[mt][nf][0] = acc[mt][nf][1] = acc[mt][nf][2] = acc[mt][nf][3] = 0.0f;
        }
}

// ---------------- kernel 0: weight prep (split + fragment pack) ----------------
__device__ __forceinline__ int fidx(int ke, int n, int split) {
    int chunk = ke >> 6, ks = (ke >> 4) & 3, r = (ke >> 3) & 1, l4 = (ke >> 1) & 3;
    int nf = n >> 3, lane = (n & 7) * 4 + l4;
    return (((chunk * 2 + split) * 4 + ks) * 16 + nf) * 64 + lane * 2 + r;
}

__global__ void prep_weights(const float* __restrict__ W1a, const float* __restrict__ W1b,
                             const float* __restrict__ W2a, const float* __restrict__ W2b) {
    int total = 16384 + 3 * 8192;
    for (int i = blockIdx.x * blockDim.x + threadIdx.x; i < total;
         i += gridDim.x * blockDim.x) {
        int j = i;
        const float* W;
        u32* G;
        if (j < 16384) {
            W = W1a;
            G = g_w1a_f;
        } else {
            j -= 16384;
            int ws = j / 8192;
            j %= 8192;
            W = (ws == 0) ? W1b : (ws == 1) ? W2a : W2b;
            G = (ws == 0) ? g_w1b_f : (ws == 1) ? g_w2a_f : g_w2b_f;
        }
        int ke = (j >> 7) * 2, n = j & 127;
        float x0 = W[ke * 128 + n], x1 = W[(ke + 1) * 128 + n];
        u32 H, L;
        split2(x0, x1, H, L);
        G[fidx(ke, n, 0)] = H;
        G[fidx(ke, n, 1)] = L;
    }
}

// ---------------- kernel 1: g_agg = node_feats ----------------
__global__ void init_agg_kernel(const float* __restrict__ node_feats, int total4) {
    int i = blockIdx.x * blockDim.x + threadIdx.x;
    int stride = gridDim.x * blockDim.x;
    const float4* s = (const float4*)node_feats;
    float4* d = (float4*)g_agg;
    for (; i < total4; i += stride) d[i] = s[i];
}

// ---------------- kernel 2: edge MLP + scatter ----------------
extern __shared__ char dynraw[];

__global__ __launch_bounds__(128, 2) void edge_kernel(
    const float* __restrict__ node_feats, const float* __restrict__ edge_feats,
    const int* __restrict__ src, const int* __restrict__ dst,
    const float* __restrict__ b1a, const float* __restrict__ b1b, int n_edges) {
    __shared__ int s_src[128], s_dst[128];
    __shared__ float s_ba[FEAT], s_bb[FEAT];

    const int tid = threadIdx.x;
    const int wid = tid >> 5, lane = tid & 31;
    const int m0 = wid * 32;
    const u32 smb = smem_u32(dynraw);
    const u32 sA = smb;                        // A1 tiles (alias hidden region)
    const u32 wbase = smb + (u32)wid * 16384;  // this warp's hidden fragments
    const u32 sB = smb + SB_OFF;

    const int e0 = blockIdx.x * 128;
    {
        int e = min(e0 + tid, n_edges - 1);
        s_src[tid] = __ldg(src + e);
        s_dst[tid] = __ldg(dst + e);
        s_ba[tid] = __ldg(b1a + tid);
        s_bb[tid] = __ldg(b1b + tid);
    }
    __syncthreads();

    float acc[2][16][4];
#pragma unroll
    for (int mt = 0; mt < 2; mt++)
#pragma unroll
        for (int i = 0; i < 16; i++)
#pragma unroll
            for (int j = 0; j < 4; j++) acc[mt][i][j] = 0.0f;

    // ---- layer 1: K=256, 4 chunks ----
    for (int c = 0; c < 4; c++) {
        cp_w(g_w1a_f + c * 8192, sB, tid);
        const float* rp;
        if (c < 2)
            rp = node_feats + (size_t)s_src[tid] * FEAT + c * 64;
        else
            rp = edge_feats + (size_t)(e0 + tid) * FEAT + (c - 2) * 64;
        u32 d = sA + (u32)tid * A1_STRIDE;
        conv32(rp, d, d + A1_TILEB);
        conv32(rp + 32, d + 64, d + 64 + A1_TILEB);
        CP_WAIT();
        __syncthreads();
        gemm1(sA + (u32)m0 * A1_STRIDE, sB, acc, lane);
        __syncthreads();
    }

    // ---- epilogue 1: relu -> hidden fragments (alias A1 region; synced above) ----
    epi_to_hfrag(acc, s_ba, wbase, lane);
    __syncthreads();

    // ---- layer 2: K=128, 2 chunks ----
    for (int c = 0; c < 2; c++) {
        cp_w(g_w1b_f + c * 8192, sB, tid);
        CP_WAIT();
        __syncthreads();
        gemm2(wbase, sB, acc, lane, c * 4);
        __syncthreads();
    }

    // ---- epilogue 2: scatter (acc + b1b) into g_agg ----
    const int rr = lane >> 2, c2 = (lane & 3) * 2;
#pragma unroll
    for (int mt = 0; mt < 2; mt++) {
        const int r0 = m0 + mt * 16 + rr, r1 = r0 + 8;
        float* p0 = g_agg + (size_t)s_dst[r0] * FEAT;
        float* p1 = g_agg + (size_t)s_dst[r1] * FEAT;
        const bool ok0 = (e0 + r0 < n_edges), ok1 = (e0 + r1 < n_edges);
#pragma unroll
        for (int nf = 0; nf < 16; nf++) {
            int n0 = nf * 8 + c2;
            if (ok0) {
                atomicAdd(p0 + n0, acc[mt][nf][0] + s_bb[n0]);
                atomicAdd(p0 + n0 + 1, acc[mt][nf][1] + s_bb[n0 + 1]);
            }
            if (ok1) {
                atomicAdd(p1 + n0, acc[mt][nf][2] + s_bb[n0]);
                atomicAdd(p1 + n0 + 1, acc[mt][nf][3] + s_bb[n0 + 1]);
            }
        }
    }
}

// ---------------- kernel 3: node MLP ----------------
__global__ __launch_bounds__(128, 2) void node_kernel(const float* __restrict__ b2a,
                                                      const float* __restrict__ b2b,
                                                      float* __restrict__ out, int n_nodes) {
    __shared__ float s_ba[FEAT], s_bb[FEAT];

    const int tid = threadIdx.x;
    const int wid = tid >> 5, lane = tid & 31;
    const int m0 = wid * 32;
    const u32 smb = smem_u32(dynraw);
    const u32 sA = smb;
    const u32 wbase = smb + (u32)wid * 16384;
    const u32 sB = smb + SB_OFF;

    const int v0 = blockIdx.x * 128;
    s_ba[tid] = __ldg(b2a + tid);
    s_bb[tid] = __ldg(b2b + tid);
    __syncthreads();

    float acc[2][16][4];
#pragma unroll
    for (int mt = 0; mt < 2; mt++)
#pragma unroll
        for (int i = 0; i < 16; i++)
#pragma unroll
            for (int j = 0; j < 4; j++) acc[mt][i][j] = 0.0f;

    // ---- layer 1: h @ W2a, K=128, 2 chunks ----
    for (int c = 0; c < 2; c++) {
        cp_w(g_w2a_f + c * 8192, sB, tid);
        const float* rp = g_agg + (size_t)min(v0 + tid, n_nodes - 1) * FEAT + c * 64;
        u32 d = sA + (u32)tid * A1_STRIDE;
        conv32(rp, d, d + A1_TILEB);
        conv32(rp + 32, d + 64, d + 64 + A1_TILEB);
        CP_WAIT();
        __syncthreads();
        gemm1(sA + (u32)m0 * A1_STRIDE, sB, acc, lane);
        __syncthreads();
    }

    // ---- epilogue 1: relu -> hidden fragments ----
    epi_to_hfrag(acc, s_ba, wbase, lane);
    __syncthreads();

    // ---- layer 2: hidden @ W2b ----
    for (int c = 0; c < 2; c++) {
        cp_w(g_w2b_f + c * 8192, sB, tid);
        CP_WAIT();
        __syncthreads();
        gemm2(wbase, sB, acc, lane, c * 4);
        __syncthreads();
    }

    // ---- epilogue 2: out = acc + b2b ----
    const int rr = lane >> 2, c2 = (lane & 3) * 2;
#pragma unroll
    for (int mt = 0; mt < 2; mt++) {
        const int r0 = m0 + mt * 16 + rr, r1 = r0 + 8;
#pragma unroll
        for (int nf = 0; nf < 16; nf++) {
            int n0 = nf * 8 + c2;
            if (v0 + r0 < n_nodes) {
                float2 v = make_float2(acc[mt][nf][0] + s_bb[n0],
                                       acc[mt][nf][1] + s_bb[n0 + 1]);
                *(float2*)(out + (size_t)(v0 + r0) * FEAT + n0) = v;
            }
            if (v0 + r1 < n_nodes) {
                float2 v = make_float2(acc[mt][nf][2] + s_bb[n0],
                                       acc[mt][nf][3] + s_bb[n0 + 1]);
                *(float2*)(out + (size_t)(v0 + r1) * FEAT + n0) = v;
            }
        }
    }
}

// ---------------- launch ----------------
extern "C" void kernel_launch(void* const* d_in, const int* in_sizes, int n_in,
                              void* d_out, int out_size) {
    const float* node_feats = (const float*)d_in[0];
    const float* edge_feats = (const float*)d_in[1];
    const int* src = (const int*)d_in[2];
    const int* dst = (const int*)d_in[3];
    const float* W1a = (const float*)d_in[4];
    const float* b1a = (const float*)d_in[5];
    const float* W1b = (const float*)d_in[6];
    const float* b1b = (const float*)d_in[7];
    const float* W2a = (const float*)d_in[8];
    const float* b2a = (const float*)d_in[9];
    const float* W2b = (const float*)d_in[10];
    const float* b2b = (const float*)d_in[11];
    float* out = (float*)d_out;

    const int n_nodes = in_sizes[0] / FEAT;
    const int n_edges = in_sizes[2];

    cudaFuncSetAttribute(edge_kernel, cudaFuncAttributeMaxDynamicSharedMemorySize,
                         DYN_BYTES);
    cudaFuncSetAttribute(node_kernel, cudaFuncAttributeMaxDynamicSharedMemorySize,
                         DYN_BYTES);

    prep_weights<<<160, 256>>>(W1a, W1b, W2a, W2b);
    init_agg_kernel<<<512, 256>>>(node_feats, n_nodes * (FEAT / 4));

    int edge_blocks = (n_edges + 127) / 128;
    edge_kernel<<<edge_blocks, 128, DYN_BYTES>>>(node_feats, edge_feats, src, dst, b1a,
                                                 b1b, n_edges);

    int node_blocks = (n_nodes + 127) / 128;
    node_kernel<<<node_blocks, 128, DYN_BYTES>>>(b2a, b2b, out, n_nodes);
}